// round 4
// baseline (speedup 1.0000x reference)
#include <cuda_runtime.h>

#define NN   116
#define NE   6670
#define HID  64
#define ENCD 122
#define G1   16      // K_A blocks: each owns a 4-wide h slice
#define G2   16      // K_BC blocks: each owns 7-8 nodes

// ---- device scratch ----
__device__ float g_dvp[G1 * NN];        // partial dv per h-slice block
__device__ __align__(16) float g_qp[G1 * NN * 4];  // partial q per h-slice block

__device__ __forceinline__ int rowoff(int a) { return a * (231 - a) / 2; }  // triu row start

// ============================================================================
// K_A: per block b, h-slice [4b, 4b+4):
//   Wz = W_enc@W1 slice, bz = b_enc@W1 slice, Wc = W2@Wl slice, d1 (full, redundant),
//   z1 slice, x1 slice = relu(b1 + sum_k d1*z1), partial dv/q -> g_dvp/g_qp.
//   Block 0 also seeds out with bl + b2@Wl.
// ============================================================================
__global__ void __launch_bounds__(256, 1) kA(
    const float* __restrict__ enc, const float* __restrict__ ea,
    const float* __restrict__ W_enc, const float* __restrict__ b_enc,
    const float* __restrict__ W1, const float* __restrict__ b1,
    const float* __restrict__ p1, const float* __restrict__ pe,
    const float* __restrict__ W2, const float* __restrict__ b2,
    const float* __restrict__ Wl, const float* __restrict__ bl,
    float* __restrict__ out)
{
    __shared__ float sWz[ENCD * 4];
    __shared__ float sbz[4];
    __shared__ float sz1[NN * 4];
    __shared__ float sd1[NE];
    __shared__ float sWc4[16];
    __shared__ float spe[4];

    const int b = blockIdx.x, t = threadIdx.x;
    const int h0 = b * 4;

    // Wz slice: Wz[k][c] = sum_m W_enc[k,m] * W1[m, h0+c]
    for (int idx = t; idx < ENCD * 4; idx += 256) {
        int k = idx >> 2, c = idx & 3, h = h0 + c;
        float s = 0.f;
        #pragma unroll 8
        for (int m = 0; m < HID; m++) s += W_enc[k * HID + m] * W1[m * HID + h];
        sWz[idx] = s;
    }
    if (t < 4) {
        int h = h0 + t;
        float s = 0.f;
        #pragma unroll 8
        for (int m = 0; m < HID; m++) s += b_enc[m] * W1[m * HID + h];
        sbz[t] = s;
        spe[t] = pe[h];
    }
    if (t >= 32 && t < 48) {   // Wc slice: Wc[h0+c][o] = sum_m W2[h0+c, m] * Wl[m, o]
        int c = (t - 32) >> 2, o = t & 3, k = h0 + c;
        float s = 0.f;
        #pragma unroll 8
        for (int m = 0; m < HID; m++) s += W2[k * HID + m] * Wl[m * 4 + o];
        sWc4[c * 4 + o] = s;
    }
    if (b == 0 && t >= 64 && t < 68) {  // seed out with bias term
        int o = t - 64;
        float s = bl[o];
        #pragma unroll 8
        for (int m = 0; m < HID; m++) s += b2[m] * Wl[m * 4 + o];
        out[o] = s;
    }
    // full d1 (redundant per block)
    for (int e = t; e < NE; e += 256) {
        const float* A = ea + e * 5;
        sd1[e] = A[0] * p1[0] + A[1] * p1[1] + A[2] * p1[2] + A[3] * p1[3] + A[4] * p1[4];
    }
    __syncthreads();

    // z1 slice: z1[i][c] = bz[c] + enc[i,:] . Wz[:,c]
    for (int idx = t; idx < NN * 4; idx += 256) {
        int i = idx >> 2, c = idx & 3;
        float s = sbz[c];
        const float* E = enc + i * ENCD;
        #pragma unroll 8
        for (int k = 0; k < ENCD; k++) s += E[k] * sWz[k * 4 + c];
        sz1[idx] = s;
    }
    __syncthreads();

    // x1 slice + partial dv/q
    #pragma unroll
    for (int r = 0; r < 2; ++r) {
        int idx = t + r * 256;
        bool act = idx < NN * 4;
        int idxc = min(idx, NN * 4 - 1);
        int i = idxc >> 2, c = idxc & 3;
        float acc = b1[h0 + c];
        const int offi = rowoff(i);
        #pragma unroll 4
        for (int u = 0; u < NN - 1; ++u) {
            int k = u + (u >= i);
            int e = (k < i) ? rowoff(k) + i - k - 1 : offi + k - i - 1;
            acc += sd1[e] * sz1[k * 4 + c];
        }
        float x = fmaxf(acc, 0.f);
        float v0 = x * sWc4[c * 4 + 0], v1 = x * sWc4[c * 4 + 1];
        float v2 = x * sWc4[c * 4 + 2], v3 = x * sWc4[c * 4 + 3];
        float v4 = x * spe[c];
        // sum over the 4 c-lanes (groups aligned; all 32 lanes participate)
        v0 += __shfl_xor_sync(0xffffffffu, v0, 1); v0 += __shfl_xor_sync(0xffffffffu, v0, 2);
        v1 += __shfl_xor_sync(0xffffffffu, v1, 1); v1 += __shfl_xor_sync(0xffffffffu, v1, 2);
        v2 += __shfl_xor_sync(0xffffffffu, v2, 1); v2 += __shfl_xor_sync(0xffffffffu, v2, 2);
        v3 += __shfl_xor_sync(0xffffffffu, v3, 1); v3 += __shfl_xor_sync(0xffffffffu, v3, 2);
        v4 += __shfl_xor_sync(0xffffffffu, v4, 1); v4 += __shfl_xor_sync(0xffffffffu, v4, 2);
        if (act && c == 0) {
            g_dvp[b * NN + i] = v4;
            ((float4*)g_qp)[b * NN + i] = make_float4(v0, v1, v2, v3);
        }
    }
}

// ============================================================================
// K_BC: per block: dv = sum of partials; full S via edge scatter (smem atomics,
//   gE recomputed inline from ea); then D for owned nodes + atomic out.
// ============================================================================
__global__ void __launch_bounds__(256, 1) kBC(
    const float* __restrict__ ea, const float* __restrict__ We,
    const float* __restrict__ be, const float* __restrict__ p2,
    float* __restrict__ out)
{
    __shared__ float sdv[NN];
    __shared__ float sS[NN * 5];
    __shared__ float sWe[25], sbe[5], sp2[5];

    const int b = blockIdx.x, t = threadIdx.x;
    const int base = (b < 4) ? 8 * b : 32 + 7 * (b - 4);
    const int cnt  = (b < 4) ? 8 : 7;
    const int wq = t >> 5, lane = t & 31;

    if (t < 25) sWe[t] = We[t];
    if (t >= 32 && t < 37) sbe[t - 32] = be[t - 32];
    if (t >= 64 && t < 69) sp2[t - 64] = p2[t - 64];
    if (t < NN) {
        float s = 0.f;
        #pragma unroll
        for (int bb = 0; bb < G1; bb++) s += g_dvp[bb * NN + t];
        sdv[t] = s;
    }
    for (int u = t; u < NN * 5; u += 256) sS[u] = 0.f;
    __syncthreads();

    // scatter pass over a contiguous edge chunk per thread
    {
        const int CH = 27;                 // 27*256 >= 6670
        int e0 = t * CH, e1 = min(e0 + CH, NE);
        int a = 0;
        while (a < 114 && rowoff(a + 1) <= e0) a++;
        int nxt = rowoff(a + 1);
        for (int e = e0; e < e1; ++e) {
            while (e >= nxt) { a++; nxt = rowoff(a + 1); }
            int bn = a + 1 + (e - rowoff(a));
            const float* A = ea + e * 5;
            float r[5];
            #pragma unroll
            for (int c = 0; c < 5; c++) r[c] = fmaxf(A[c], 0.f);
            float inv = 1.f / (fmaxf(fmaxf(sdv[a], sdv[bn]), 0.f) + 1e-10f);
            #pragma unroll
            for (int c2 = 0; c2 < 5; c2++) {
                float g = r[0] * sWe[c2] + r[1] * sWe[5 + c2] + r[2] * sWe[10 + c2]
                        + r[3] * sWe[15 + c2] + r[4] * sWe[20 + c2];
                float h = g * inv;
                atomicAdd(&sS[a * 5 + c2], h);
                atomicAdd(&sS[bn * 5 + c2], h);
            }
        }
    }
    __syncthreads();

    // D for owned nodes (warp per node), then output accumulation
    {
        int i = min(base + wq, NN - 1);
        bool valid = wq < cnt;
        float dvi = sdv[i];
        const int offi = rowoff(i);
        float partv = 0.f;
        #pragma unroll
        for (int q = 0; q < 4; ++q) {
            int u = lane + q * 32;
            if (u < NN - 1) {
                int k = u + (u >= i);
                int e = (k < i) ? rowoff(k) + i - k - 1 : offi + k - i - 1;
                const float* A = ea + e * 5;
                float r[5];
                #pragma unroll
                for (int c = 0; c < 5; c++) r[c] = fmaxf(A[c], 0.f);
                float dvk = sdv[k];
                float inv = 1.f / (fmaxf(fmaxf(dvi, dvk), 0.f) + 1e-10f);
                #pragma unroll
                for (int c2 = 0; c2 < 5; c2++) {
                    float g = r[0] * sWe[c2] + r[1] * sWe[5 + c2] + r[2] * sWe[10 + c2]
                            + r[3] * sWe[15 + c2] + r[4] * sWe[20 + c2];
                    float hh = g * inv;
                    float v = dvi * (sS[i * 5 + c2] - hh) + dvk * (sS[k * 5 + c2] - hh) + sbe[c2];
                    partv += fmaxf(v, 0.f) * sp2[c2];
                }
            }
        }
        #pragma unroll
        for (int off = 16; off; off >>= 1) partv += __shfl_down_sync(0xffffffffu, partv, off);
        partv = __shfl_sync(0xffffffffu, partv, 0);
        if (valid && lane < 4) {
            float qv = 0.f;
            #pragma unroll
            for (int bb = 0; bb < G1; bb++) qv += g_qp[(bb * NN + i) * 4 + lane];
            atomicAdd(&out[lane], partv * (1.0f / (float)NN) * qv);
        }
    }
}

extern "C" void kernel_launch(void* const* d_in, const int* in_sizes, int n_in,
                              void* d_out, int out_size) {
    const float* enc   = (const float*)d_in[0];
    const float* ea    = (const float*)d_in[1];
    // d_in[2] = edge_index (triu order, closed-form reproduced) — unused
    const float* W_enc = (const float*)d_in[3];
    const float* b_enc = (const float*)d_in[4];
    const float* W1    = (const float*)d_in[5];
    const float* b1    = (const float*)d_in[6];
    const float* p1    = (const float*)d_in[7];
    const float* We    = (const float*)d_in[8];
    const float* be    = (const float*)d_in[9];
    const float* pe    = (const float*)d_in[10];
    const float* W2    = (const float*)d_in[11];
    const float* b2    = (const float*)d_in[12];
    const float* p2    = (const float*)d_in[13];
    const float* Wl    = (const float*)d_in[14];
    const float* bl    = (const float*)d_in[15];
    float* out = (float*)d_out;

    kA<<<G1, 256>>>(enc, ea, W_enc, b_enc, W1, b1, p1, pe, W2, b2, Wl, bl, out);
    kBC<<<G2, 256>>>(ea, We, be, p2, out);
}

// round 6
// speedup vs baseline: 4.7111x; 4.7111x over previous
#include <cuda_runtime.h>

#define NN   116
#define NE   6670
#define HID  64
#define ENCD 122

// ---- device scratch ----
__device__ float g_gE[NE * 5];
__device__ float g_dv[NN];
__device__ __align__(16) float g_q[NN * 4];   // pre-scaled by 1/NN
__device__ float g_S[NN * 5];

__device__ __forceinline__ int rowoff(int a) { return a * (231 - a) / 2; }
__device__ __forceinline__ int eix(int a, int b) { return rowoff(a) + (b - a - 1); }

// ============================================================================
// K1: block per node i. Computes x1[i] WITHOUT other nodes' z1 via
//   x1[i] = relu(b1 + (M_i @ W_enc + s_i*b_enc) @ W1),  M_i = sum_k d1[ik]*enc[k,:]
// then dv[i] = x1.pe, q[i] = ((x1@W2)@Wl)/NN. Also writes gE row, bias seed.
// ============================================================================
__global__ void __launch_bounds__(256, 1) k1(
    const float* __restrict__ enc, const float* __restrict__ ea,
    const float* __restrict__ W_enc, const float* __restrict__ b_enc,
    const float* __restrict__ W1, const float* __restrict__ b1,
    const float* __restrict__ p1, const float* __restrict__ We,
    const float* __restrict__ pe, const float* __restrict__ W2,
    const float* __restrict__ b2, const float* __restrict__ Wl,
    const float* __restrict__ bl, float* __restrict__ out)
{
    __shared__ float sd1[116];
    __shared__ float sMp[2 * 123];
    __shared__ float sM[123];          // sM[122] = s_i
    __shared__ float sp[256];
    __shared__ float sy[64];
    __shared__ float sx1[64];
    __shared__ float sw[64];

    const int i = blockIdx.x, t = threadIdx.x;

    // bias seed: out = bl + b2 @ Wl  (block 0 only, 4 threads, plain loop)
    if (i == 0 && t < 4) {
        float s = bl[t];
        #pragma unroll 8
        for (int m = 0; m < HID; m++) s += b2[m] * Wl[m * 4 + t];
        out[t] = s;
    }

    // d1 row + gE row (1 edge per thread)
    if (t < 115) {
        int k = t + (t >= i);
        int a = min(i, k), b = max(i, k);
        int e = eix(a, b);
        const float* A = ea + e * 5;
        float a5[5], r5[5];
        #pragma unroll
        for (int c = 0; c < 5; c++) { a5[c] = A[c]; r5[c] = fmaxf(a5[c], 0.f); }
        sd1[t] = a5[0] * __ldg(&p1[0]) + a5[1] * __ldg(&p1[1]) + a5[2] * __ldg(&p1[2])
               + a5[3] * __ldg(&p1[3]) + a5[4] * __ldg(&p1[4]);
        if (a == i) {  // write each edge's gE exactly once (row-owner block)
            #pragma unroll
            for (int c2 = 0; c2 < 5; c2++) {
                float g = r5[0] * __ldg(&We[c2]) + r5[1] * __ldg(&We[5 + c2])
                        + r5[2] * __ldg(&We[10 + c2]) + r5[3] * __ldg(&We[15 + c2])
                        + r5[4] * __ldg(&We[20 + c2]);
                g_gE[e * 5 + c2] = g;
            }
        }
    }
    __syncthreads();

    // M stage: 2 threads per col (123 cols; col 122 accumulates plain sum of d1)
    if (t < 246) {
        int c = t >> 1, half = t & 1;
        int u0 = half ? 58 : 0, u1 = half ? 115 : 58;
        float s = 0.f;
        if (c < 122) {
            #pragma unroll 4
            for (int u = u0; u < u1; ++u) {
                int k = u + (u >= i);
                s += sd1[u] * enc[k * ENCD + c];
            }
        } else {
            #pragma unroll 4
            for (int u = u0; u < u1; ++u) s += sd1[u];
        }
        sMp[half * 123 + c] = s;
    }
    __syncthreads();
    if (t < 123) sM[t] = sMp[t] + sMp[123 + t];
    __syncthreads();

    // y = M @ W_enc + s_i * b_enc : 4 threads per m, ~31 cols each
    {
        int m = t >> 2, qd = t & 3;
        int c0 = qd * 31, c1 = min(c0 + 31, 123);
        float s = 0.f;
        for (int c = c0; c < c1; ++c) {
            float w = (c < 122) ? W_enc[c * HID + m] : b_enc[m];
            s += sM[c] * w;
        }
        sp[t] = s;
    }
    __syncthreads();
    if (t < HID) sy[t] = sp[t * 4] + sp[t * 4 + 1] + sp[t * 4 + 2] + sp[t * 4 + 3];
    __syncthreads();

    // x1 = relu(b1 + y @ W1) : 4 threads per h, 16 rows each
    {
        int h = t >> 2, qd = t & 3;
        float s = 0.f;
        #pragma unroll
        for (int j = 0; j < 16; ++j) { int m = qd * 16 + j; s += sy[m] * W1[m * HID + h]; }
        sp[t] = s;
    }
    __syncthreads();
    if (t < HID) sx1[t] = fmaxf(b1[t] + sp[t * 4] + sp[t * 4 + 1] + sp[t * 4 + 2] + sp[t * 4 + 3], 0.f);
    __syncthreads();

    // w = x1 @ W2 : same shape
    {
        int h = t >> 2, qd = t & 3;
        float s = 0.f;
        #pragma unroll
        for (int j = 0; j < 16; ++j) { int m = qd * 16 + j; s += sx1[m] * W2[m * HID + h]; }
        sp[t] = s;
    }
    __syncthreads();
    if (t < HID) sw[t] = sp[t * 4] + sp[t * 4 + 1] + sp[t * 4 + 2] + sp[t * 4 + 3];
    __syncthreads();

    // warp 0: q[o] = (w @ Wl)[o] / NN   (8 threads per o)
    if (t < 32) {
        int o = t >> 3, oc = t & 7;
        float s = 0.f;
        #pragma unroll
        for (int j = 0; j < 8; ++j) { int m = oc * 8 + j; s += sw[m] * Wl[m * 4 + o]; }
        s += __shfl_xor_sync(0xffffffffu, s, 1);
        s += __shfl_xor_sync(0xffffffffu, s, 2);
        s += __shfl_xor_sync(0xffffffffu, s, 4);
        if (oc == 0) g_q[i * 4 + o] = s * (1.0f / (float)NN);
    }
    // warp 1: dv = x1 . pe
    if (t >= 32 && t < 64) {
        int l = t - 32;
        float s = sx1[l] * pe[l] + sx1[l + 32] * pe[l + 32];
        #pragma unroll
        for (int off = 16; off; off >>= 1) s += __shfl_xor_sync(0xffffffffu, s, off);
        if (l == 0) g_dv[i] = s;
    }
}

// ============================================================================
// K2: S[i,c] = sum over 115 edges of gE/(max(dv_i,dv_k,0)+eps)
// ============================================================================
__global__ void __launch_bounds__(128, 1) k2(float* dummy)
{
    __shared__ float sdv[NN];
    __shared__ float wsum[4 * 5];
    const int i = blockIdx.x, t = threadIdx.x;
    const int wq = t >> 5, lane = t & 31;

    if (t < NN) sdv[t] = g_dv[t];
    __syncthreads();

    float a5[5] = {0.f, 0.f, 0.f, 0.f, 0.f};
    if (t < 115) {
        int k = t + (t >= i);
        int a = min(i, k), b = max(i, k);
        int e = eix(a, b);
        float inv = 1.f / (fmaxf(fmaxf(sdv[i], sdv[k]), 0.f) + 1e-10f);
        #pragma unroll
        for (int c = 0; c < 5; c++) a5[c] = g_gE[e * 5 + c] * inv;
    }
    #pragma unroll
    for (int c = 0; c < 5; c++) {
        #pragma unroll
        for (int off = 16; off; off >>= 1) a5[c] += __shfl_xor_sync(0xffffffffu, a5[c], off);
        if (lane == 0) wsum[wq * 5 + c] = a5[c];
    }
    __syncthreads();
    if (t < 5) g_S[i * 5 + t] = wsum[t] + wsum[5 + t] + wsum[10 + t] + wsum[15 + t];
}

// ============================================================================
// K3: D[i] then out[o] += D[i] * q[i,o]   (q pre-scaled by 1/NN)
// ============================================================================
__global__ void __launch_bounds__(128, 1) k3(
    const float* __restrict__ be, const float* __restrict__ p2,
    float* __restrict__ out)
{
    __shared__ float sdv[NN];
    __shared__ float sS[NN * 5];
    __shared__ float wred[4];
    const int i = blockIdx.x, t = threadIdx.x;
    const int wq = t >> 5, lane = t & 31;

    if (t < NN) sdv[t] = g_dv[t];
    for (int u = t; u < NN * 5; u += 128) sS[u] = g_S[u];
    __syncthreads();

    float dvi = sdv[i];
    float partv = 0.f;
    if (t < 115) {
        int k = t + (t >= i);
        int a = min(i, k), b = max(i, k);
        int e = eix(a, b);
        float dvk = sdv[k];
        float inv = 1.f / (fmaxf(fmaxf(dvi, dvk), 0.f) + 1e-10f);
        #pragma unroll
        for (int c = 0; c < 5; c++) {
            float hh = g_gE[e * 5 + c] * inv;
            float v = dvi * (sS[i * 5 + c] - hh) + dvk * (sS[k * 5 + c] - hh) + __ldg(&be[c]);
            partv += fmaxf(v, 0.f) * __ldg(&p2[c]);
        }
    }
    #pragma unroll
    for (int off = 16; off; off >>= 1) partv += __shfl_xor_sync(0xffffffffu, partv, off);
    if (lane == 0) wred[wq] = partv;
    __syncthreads();
    if (t < 4) {
        float D = wred[0] + wred[1] + wred[2] + wred[3];
        atomicAdd(&out[t], D * g_q[i * 4 + t]);
    }
}

extern "C" void kernel_launch(void* const* d_in, const int* in_sizes, int n_in,
                              void* d_out, int out_size) {
    const float* enc   = (const float*)d_in[0];
    const float* ea    = (const float*)d_in[1];
    // d_in[2] = edge_index (triu order, closed-form reproduced) — unused
    const float* W_enc = (const float*)d_in[3];
    const float* b_enc = (const float*)d_in[4];
    const float* W1    = (const float*)d_in[5];
    const float* b1    = (const float*)d_in[6];
    const float* p1    = (const float*)d_in[7];
    const float* We    = (const float*)d_in[8];
    const float* be    = (const float*)d_in[9];
    const float* pe    = (const float*)d_in[10];
    const float* W2    = (const float*)d_in[11];
    const float* b2    = (const float*)d_in[12];
    const float* p2    = (const float*)d_in[13];
    const float* Wl    = (const float*)d_in[14];
    const float* bl    = (const float*)d_in[15];
    float* out = (float*)d_out;

    k1<<<NN, 256>>>(enc, ea, W_enc, b_enc, W1, b1, p1, We, pe, W2, b2, Wl, bl, out);
    k2<<<NN, 128>>>(out);
    k3<<<NN, 128>>>(be, p2, out);
}

// round 7
// speedup vs baseline: 5.2228x; 1.1086x over previous
#include <cuda_runtime.h>

#define NN   116
#define NE   6670
#define HID  64
#define ENCD 122

// ---- device scratch ----
__device__ float g_gE[NE * 5];
__device__ float g_dv[NN];
__device__ __align__(16) float g_q[NN * 4];   // pre-scaled by 1/NN
__device__ float g_S[NN * 5];

__device__ __forceinline__ int rowoff(int a) { return a * (231 - a) / 2; }
__device__ __forceinline__ int eix(int a, int b) { return rowoff(a) + (b - a - 1); }

// ============================================================================
// K1 (512 thr): block per node i.
//   x1[i] = relu(b1 + (M_i @ [W_enc; b_enc; 0]) @ W1),  M_i = sum_k d1[ik]*enc[k,:] (+s_i)
//   dv[i] = x1.pe,  q[i] = ((x1@W2)@Wl)/NN.  Also gE row (row-owner), bias seed.
// All inner loops have compile-time trip counts and are fully unrolled.
// ============================================================================
__global__ void __launch_bounds__(512, 1) k1(
    const float* __restrict__ enc, const float* __restrict__ ea,
    const float* __restrict__ W_enc, const float* __restrict__ b_enc,
    const float* __restrict__ W1, const float* __restrict__ b1,
    const float* __restrict__ p1, const float* __restrict__ We,
    const float* __restrict__ pe, const float* __restrict__ W2,
    const float* __restrict__ b2, const float* __restrict__ Wl,
    const float* __restrict__ bl, float* __restrict__ out)
{
    __shared__ float sd1[116];
    __shared__ float sMp[4 * 123];
    __shared__ float sM[124];          // [122]=s_i (bias lane), [123]=0
    __shared__ float sp[512];
    __shared__ float sy[64];
    __shared__ float sx1[64];
    __shared__ float sw[64];

    const int i = blockIdx.x, t = threadIdx.x;

    // bias seed: out = bl + b2 @ Wl  (block 0 only)
    if (i == 0 && t < 4) {
        float s = bl[t];
        #pragma unroll
        for (int m = 0; m < HID; m++) s += b2[m] * Wl[m * 4 + t];
        out[t] = s;
    }

    // d1 row + gE row (1 edge per thread; gE written once by row-owner block)
    if (t < 115) {
        int k = t + (t >= i);
        int a = min(i, k), b = max(i, k);
        int e = eix(a, b);
        const float* A = ea + e * 5;
        float a5[5], r5[5];
        #pragma unroll
        for (int c = 0; c < 5; c++) { a5[c] = A[c]; r5[c] = fmaxf(a5[c], 0.f); }
        sd1[t] = a5[0] * __ldg(&p1[0]) + a5[1] * __ldg(&p1[1]) + a5[2] * __ldg(&p1[2])
               + a5[3] * __ldg(&p1[3]) + a5[4] * __ldg(&p1[4]);
        if (a == i) {
            #pragma unroll
            for (int c2 = 0; c2 < 5; c2++) {
                float g = r5[0] * __ldg(&We[c2]) + r5[1] * __ldg(&We[5 + c2])
                        + r5[2] * __ldg(&We[10 + c2]) + r5[3] * __ldg(&We[15 + c2])
                        + r5[4] * __ldg(&We[20 + c2]);
                g_gE[e * 5 + c2] = g;
            }
        }
    }
    if (t >= 504 && t < 506) sM[t - 504 + 122] = 0.f;  // placeholder; s_i set below
    __syncthreads();

    // M stage: 4 threads per col, 29 unrolled iters each (123 cols; col 122 = sum d1)
    if (t < 492) {
        int c = t >> 2, q = t & 3;
        int u0 = q * 29;
        float s = 0.f;
        if (c < 122) {
            #pragma unroll
            for (int j = 0; j < 29; ++j) {
                int u = u0 + j;
                if (u < 115) {
                    int k = u + (u >= i);
                    s += sd1[u] * enc[k * ENCD + c];
                }
            }
        } else {
            #pragma unroll
            for (int j = 0; j < 29; ++j) {
                int u = u0 + j;
                if (u < 115) s += sd1[u];
            }
        }
        sMp[q * 123 + c] = s;
    }
    __syncthreads();
    if (t < 123) sM[t] = sMp[t] + sMp[123 + t] + sMp[246 + t] + sMp[369 + t];
    if (t == 123) sM[123] = 0.f;
    __syncthreads();

    // y = M @ [W_enc; b_enc; 0] : 8 groups x 16 unrolled cols per m
    {
        int m = t & 63, g = t >> 6;
        float s = 0.f;
        #pragma unroll
        for (int j = 0; j < 16; ++j) {
            int c = g * 16 + j;
            if (c < 124) {
                float w = (c < 122) ? W_enc[c * HID + m] : ((c == 122) ? b_enc[m] : 0.f);
                s += sM[c] * w;
            }
        }
        sp[g * 64 + m] = s;
    }
    __syncthreads();
    if (t < HID) {
        float s = sp[t];
        #pragma unroll
        for (int g = 1; g < 8; ++g) s += sp[g * 64 + t];
        sy[t] = s;
    }
    __syncthreads();

    // x1 = relu(b1 + y @ W1) : 8 groups x 8 rows per h
    {
        int h = t & 63, g = t >> 6;
        float s = 0.f;
        #pragma unroll
        for (int j = 0; j < 8; ++j) { int m = g * 8 + j; s += sy[m] * W1[m * HID + h]; }
        sp[g * 64 + h] = s;
    }
    __syncthreads();
    if (t < HID) {
        float s = sp[t];
        #pragma unroll
        for (int g = 1; g < 8; ++g) s += sp[g * 64 + t];
        sx1[t] = fmaxf(b1[t] + s, 0.f);
    }
    __syncthreads();

    // w = x1 @ W2 : same shape
    {
        int h = t & 63, g = t >> 6;
        float s = 0.f;
        #pragma unroll
        for (int j = 0; j < 8; ++j) { int m = g * 8 + j; s += sx1[m] * W2[m * HID + h]; }
        sp[g * 64 + h] = s;
    }
    __syncthreads();
    if (t < HID) {
        float s = sp[t];
        #pragma unroll
        for (int g = 1; g < 8; ++g) s += sp[g * 64 + t];
        sw[t] = s;
    }
    __syncthreads();

    // warp 0: q[o] = (w @ Wl)[o] / NN   (8 threads per o)
    if (t < 32) {
        int o = t >> 3, oc = t & 7;
        float s = 0.f;
        #pragma unroll
        for (int j = 0; j < 8; ++j) { int m = oc * 8 + j; s += sw[m] * Wl[m * 4 + o]; }
        s += __shfl_xor_sync(0xffffffffu, s, 1);
        s += __shfl_xor_sync(0xffffffffu, s, 2);
        s += __shfl_xor_sync(0xffffffffu, s, 4);
        if (oc == 0) g_q[i * 4 + o] = s * (1.0f / (float)NN);
    }
    // warp 1: dv = x1 . pe
    if (t >= 32 && t < 64) {
        int l = t - 32;
        float s = sx1[l] * pe[l] + sx1[l + 32] * pe[l + 32];
        #pragma unroll
        for (int off = 16; off; off >>= 1) s += __shfl_xor_sync(0xffffffffu, s, off);
        if (l == 0) g_dv[i] = s;
    }
}

// ============================================================================
// K2: S[i,c] = sum over 115 edges of gE/(max(dv_i,dv_k,0)+eps)
// ============================================================================
__global__ void __launch_bounds__(128, 1) k2(float* dummy)
{
    __shared__ float sdv[NN];
    __shared__ float wsum[4 * 5];
    const int i = blockIdx.x, t = threadIdx.x;
    const int wq = t >> 5, lane = t & 31;

    if (t < NN) sdv[t] = g_dv[t];
    __syncthreads();

    float a5[5] = {0.f, 0.f, 0.f, 0.f, 0.f};
    if (t < 115) {
        int k = t + (t >= i);
        int a = min(i, k), b = max(i, k);
        int e = eix(a, b);
        float inv = 1.f / (fmaxf(fmaxf(sdv[i], sdv[k]), 0.f) + 1e-10f);
        #pragma unroll
        for (int c = 0; c < 5; c++) a5[c] = g_gE[e * 5 + c] * inv;
    }
    #pragma unroll
    for (int c = 0; c < 5; c++) {
        #pragma unroll
        for (int off = 16; off; off >>= 1) a5[c] += __shfl_xor_sync(0xffffffffu, a5[c], off);
        if (lane == 0) wsum[wq * 5 + c] = a5[c];
    }
    __syncthreads();
    if (t < 5) g_S[i * 5 + t] = wsum[t] + wsum[5 + t] + wsum[10 + t] + wsum[15 + t];
}

// ============================================================================
// K3: D[i] then out[o] += D[i] * q[i,o]   (q pre-scaled by 1/NN)
// ============================================================================
__global__ void __launch_bounds__(128, 1) k3(
    const float* __restrict__ be, const float* __restrict__ p2,
    float* __restrict__ out)
{
    __shared__ float sdv[NN];
    __shared__ float sS[NN * 5];
    __shared__ float wred[4];
    const int i = blockIdx.x, t = threadIdx.x;
    const int wq = t >> 5, lane = t & 31;

    if (t < NN) sdv[t] = g_dv[t];
    for (int u = t; u < NN * 5; u += 128) sS[u] = g_S[u];
    __syncthreads();

    float dvi = sdv[i];
    float partv = 0.f;
    if (t < 115) {
        int k = t + (t >= i);
        int a = min(i, k), b = max(i, k);
        int e = eix(a, b);
        float dvk = sdv[k];
        float inv = 1.f / (fmaxf(fmaxf(dvi, dvk), 0.f) + 1e-10f);
        #pragma unroll
        for (int c = 0; c < 5; c++) {
            float hh = g_gE[e * 5 + c] * inv;
            float v = dvi * (sS[i * 5 + c] - hh) + dvk * (sS[k * 5 + c] - hh) + __ldg(&be[c]);
            partv += fmaxf(v, 0.f) * __ldg(&p2[c]);
        }
    }
    #pragma unroll
    for (int off = 16; off; off >>= 1) partv += __shfl_xor_sync(0xffffffffu, partv, off);
    if (lane == 0) wred[wq] = partv;
    __syncthreads();
    if (t < 4) {
        float D = wred[0] + wred[1] + wred[2] + wred[3];
        atomicAdd(&out[t], D * g_q[i * 4 + t]);
    }
}

extern "C" void kernel_launch(void* const* d_in, const int* in_sizes, int n_in,
                              void* d_out, int out_size) {
    const float* enc   = (const float*)d_in[0];
    const float* ea    = (const float*)d_in[1];
    // d_in[2] = edge_index (triu order, closed-form reproduced) — unused
    const float* W_enc = (const float*)d_in[3];
    const float* b_enc = (const float*)d_in[4];
    const float* W1    = (const float*)d_in[5];
    const float* b1    = (const float*)d_in[6];
    const float* p1    = (const float*)d_in[7];
    const float* We    = (const float*)d_in[8];
    const float* be    = (const float*)d_in[9];
    const float* pe    = (const float*)d_in[10];
    const float* W2    = (const float*)d_in[11];
    const float* b2    = (const float*)d_in[12];
    const float* p2    = (const float*)d_in[13];
    const float* Wl    = (const float*)d_in[14];
    const float* bl    = (const float*)d_in[15];
    float* out = (float*)d_out;

    k1<<<NN, 512>>>(enc, ea, W_enc, b_enc, W1, b1, p1, We, pe, W2, b2, Wl, bl, out);
    k2<<<NN, 128>>>(out);
    k3<<<NN, 128>>>(be, p2, out);
}

// round 8
// speedup vs baseline: 6.0108x; 1.1509x over previous
#include <cuda_runtime.h>

#define NN   116
#define NE   6670
#define HID  64
#define ENCD 122

// ---- device scratch ----
__device__ float g_gE[NE * 5];
__device__ float g_dv[NN];
__device__ __align__(16) float g_x1[NN * HID];
__device__ __align__(16) float g_Wc[HID * 4];   // W2 @ Wl
__device__ float g_S[NN * 5];

__device__ __forceinline__ int rowoff(int a) { return a * (231 - a) / 2; }
__device__ __forceinline__ int eix(int a, int b) { return rowoff(a) + (b - a - 1); }

// ============================================================================
// K1 (512 thr): block per node i.
//   x1[i] = relu(b1 + (M_i @ [W_enc; b_enc; 0]) @ W1),  M_i = sum_k d1[ik]*enc[k,:] (+s_i)
//   dv[i] = x1.pe.  Stores x1 to global (q computed in k3). Also gE row, bias seed.
// ============================================================================
__global__ void __launch_bounds__(512, 1) k1(
    const float* __restrict__ enc, const float* __restrict__ ea,
    const float* __restrict__ W_enc, const float* __restrict__ b_enc,
    const float* __restrict__ W1, const float* __restrict__ b1,
    const float* __restrict__ p1, const float* __restrict__ We,
    const float* __restrict__ pe, const float* __restrict__ b2,
    const float* __restrict__ Wl, const float* __restrict__ bl,
    float* __restrict__ out)
{
    __shared__ float sd1[116];
    __shared__ float sMp[4 * 123];
    __shared__ float sM[124];          // [122]=s_i (bias lane), [123]=0
    __shared__ float sp[512];
    __shared__ float sy[64];
    __shared__ float sx1[64];

    const int i = blockIdx.x, t = threadIdx.x;

    // bias seed: out = bl + b2 @ Wl  (block 0 only)
    if (i == 0 && t < 4) {
        float s = bl[t];
        #pragma unroll
        for (int m = 0; m < HID; m++) s += b2[m] * Wl[m * 4 + t];
        out[t] = s;
    }

    // d1 row + gE row (1 edge per thread; gE written once by row-owner block)
    if (t < 115) {
        int k = t + (t >= i);
        int a = min(i, k), b = max(i, k);
        int e = eix(a, b);
        const float* A = ea + e * 5;
        float a5[5], r5[5];
        #pragma unroll
        for (int c = 0; c < 5; c++) { a5[c] = A[c]; r5[c] = fmaxf(a5[c], 0.f); }
        sd1[t] = a5[0] * __ldg(&p1[0]) + a5[1] * __ldg(&p1[1]) + a5[2] * __ldg(&p1[2])
               + a5[3] * __ldg(&p1[3]) + a5[4] * __ldg(&p1[4]);
        if (a == i) {
            #pragma unroll
            for (int c2 = 0; c2 < 5; c2++) {
                float g = r5[0] * __ldg(&We[c2]) + r5[1] * __ldg(&We[5 + c2])
                        + r5[2] * __ldg(&We[10 + c2]) + r5[3] * __ldg(&We[15 + c2])
                        + r5[4] * __ldg(&We[20 + c2]);
                g_gE[e * 5 + c2] = g;
            }
        }
    }
    __syncthreads();

    // M stage: 4 threads per col, 29 unrolled iters each (123 cols; col 122 = sum d1)
    if (t < 492) {
        int c = t >> 2, q = t & 3;
        int u0 = q * 29;
        float s = 0.f;
        if (c < 122) {
            #pragma unroll
            for (int j = 0; j < 29; ++j) {
                int u = u0 + j;
                if (u < 115) {
                    int k = u + (u >= i);
                    s += sd1[u] * enc[k * ENCD + c];
                }
            }
        } else {
            #pragma unroll
            for (int j = 0; j < 29; ++j) {
                int u = u0 + j;
                if (u < 115) s += sd1[u];
            }
        }
        sMp[q * 123 + c] = s;
    }
    __syncthreads();
    if (t < 123) sM[t] = sMp[t] + sMp[123 + t] + sMp[246 + t] + sMp[369 + t];
    if (t == 123) sM[123] = 0.f;
    __syncthreads();

    // y = M @ [W_enc; b_enc; 0] : 8 groups x 16 unrolled cols per m
    {
        int m = t & 63, g = t >> 6;
        float s = 0.f;
        #pragma unroll
        for (int j = 0; j < 16; ++j) {
            int c = g * 16 + j;
            if (c < 124) {
                float w = (c < 122) ? W_enc[c * HID + m] : ((c == 122) ? b_enc[m] : 0.f);
                s += sM[c] * w;
            }
        }
        sp[g * 64 + m] = s;
    }
    __syncthreads();
    if (t < HID) {
        float s = sp[t];
        #pragma unroll
        for (int g = 1; g < 8; ++g) s += sp[g * 64 + t];
        sy[t] = s;
    }
    __syncthreads();

    // x1 = relu(b1 + y @ W1) : 8 groups x 8 rows per h
    {
        int h = t & 63, g = t >> 6;
        float s = 0.f;
        #pragma unroll
        for (int j = 0; j < 8; ++j) { int m = g * 8 + j; s += sy[m] * W1[m * HID + h]; }
        sp[g * 64 + h] = s;
    }
    __syncthreads();
    if (t < HID) {
        float s = sp[t];
        #pragma unroll
        for (int g = 1; g < 8; ++g) s += sp[g * 64 + t];
        float x = fmaxf(b1[t] + s, 0.f);
        sx1[t] = x;
        g_x1[i * HID + t] = x;
    }
    __syncthreads();

    // warp 0: dv = x1 . pe
    if (t < 32) {
        float s = sx1[t] * pe[t] + sx1[t + 32] * pe[t + 32];
        #pragma unroll
        for (int off = 16; off; off >>= 1) s += __shfl_xor_sync(0xffffffffu, s, off);
        if (t == 0) g_dv[i] = s;
    }
}

// ============================================================================
// K2 (PDL): blocks 0..115: S[i,c]; blocks 116,117: Wc = W2@Wl (no dependency,
// skip grid sync -> overlaps with k1 tail).
// ============================================================================
__global__ void __launch_bounds__(128, 1) k2(
    const float* __restrict__ W2, const float* __restrict__ Wl)
{
    const int i = blockIdx.x, t = threadIdx.x;

    if (i >= NN) {                       // Wc blocks: independent of k1
        int idx = (i - NN) * 128 + t;    // 0..255
        int k = idx >> 2, o = idx & 3;
        float s = 0.f;
        #pragma unroll
        for (int m = 0; m < HID; m++) s += W2[k * HID + m] * Wl[m * 4 + o];
        g_Wc[idx] = s;
        return;
    }

    cudaGridDependencySynchronize();     // wait for k1 results

    __shared__ float sdv[NN];
    __shared__ float wsum[4 * 5];
    const int wq = t >> 5, lane = t & 31;

    if (t < NN) sdv[t] = g_dv[t];
    __syncthreads();

    float a5[5] = {0.f, 0.f, 0.f, 0.f, 0.f};
    if (t < 115) {
        int k = t + (t >= i);
        int a = min(i, k), b = max(i, k);
        int e = eix(a, b);
        float inv = 1.f / (fmaxf(fmaxf(sdv[i], sdv[k]), 0.f) + 1e-10f);
        #pragma unroll
        for (int c = 0; c < 5; c++) a5[c] = g_gE[e * 5 + c] * inv;
    }
    #pragma unroll
    for (int c = 0; c < 5; c++) {
        #pragma unroll
        for (int off = 16; off; off >>= 1) a5[c] += __shfl_xor_sync(0xffffffffu, a5[c], off);
        if (lane == 0) wsum[wq * 5 + c] = a5[c];
    }
    __syncthreads();
    if (t < 5) g_S[i * 5 + t] = wsum[t] + wsum[5 + t] + wsum[10 + t] + wsum[15 + t];
}

// ============================================================================
// K3 (PDL): D[i]; then q[i] = x1[i]@Wc inline; out[o] += D * q[o] / NN
// ============================================================================
__global__ void __launch_bounds__(128, 1) k3(
    const float* __restrict__ be, const float* __restrict__ p2,
    float* __restrict__ out)
{
    cudaGridDependencySynchronize();     // wait for k2 (and transitively k1)

    __shared__ float sdv[NN];
    __shared__ float sS[NN * 5];
    __shared__ float sx1r[HID];
    __shared__ float sWc[HID * 4];
    __shared__ float wred[4];
    const int i = blockIdx.x, t = threadIdx.x;
    const int wq = t >> 5, lane = t & 31;

    if (t < NN) sdv[t] = g_dv[t];
    for (int u = t; u < NN * 5; u += 128) sS[u] = g_S[u];
    if (t < HID) sx1r[t] = g_x1[i * HID + t];
    sWc[t] = g_Wc[t];
    sWc[t + 128] = g_Wc[t + 128];
    __syncthreads();

    float dvi = sdv[i];
    float partv = 0.f;
    if (t < 115) {
        int k = t + (t >= i);
        int a = min(i, k), b = max(i, k);
        int e = eix(a, b);
        float dvk = sdv[k];
        float inv = 1.f / (fmaxf(fmaxf(dvi, dvk), 0.f) + 1e-10f);
        #pragma unroll
        for (int c = 0; c < 5; c++) {
            float hh = g_gE[e * 5 + c] * inv;
            float v = dvi * (sS[i * 5 + c] - hh) + dvk * (sS[k * 5 + c] - hh) + __ldg(&be[c]);
            partv += fmaxf(v, 0.f) * __ldg(&p2[c]);
        }
    }
    #pragma unroll
    for (int off = 16; off; off >>= 1) partv += __shfl_xor_sync(0xffffffffu, partv, off);
    if (lane == 0) wred[wq] = partv;
    __syncthreads();

    // warps 0-3: q[o] = x1 . Wc[:,o]; lane0 adds D*q[o]/NN
    {
        int o = wq;
        float qv = sx1r[lane] * sWc[lane * 4 + o] + sx1r[lane + 32] * sWc[(lane + 32) * 4 + o];
        #pragma unroll
        for (int off = 16; off; off >>= 1) qv += __shfl_xor_sync(0xffffffffu, qv, off);
        if (lane == 0) {
            float D = wred[0] + wred[1] + wred[2] + wred[3];
            atomicAdd(&out[o], D * qv * (1.0f / (float)NN));
        }
    }
}

extern "C" void kernel_launch(void* const* d_in, const int* in_sizes, int n_in,
                              void* d_out, int out_size) {
    const float* enc   = (const float*)d_in[0];
    const float* ea    = (const float*)d_in[1];
    // d_in[2] = edge_index (triu order, closed-form reproduced) — unused
    const float* W_enc = (const float*)d_in[3];
    const float* b_enc = (const float*)d_in[4];
    const float* W1    = (const float*)d_in[5];
    const float* b1    = (const float*)d_in[6];
    const float* p1    = (const float*)d_in[7];
    const float* We    = (const float*)d_in[8];
    const float* be    = (const float*)d_in[9];
    const float* pe    = (const float*)d_in[10];
    const float* W2    = (const float*)d_in[11];
    const float* b2    = (const float*)d_in[12];
    const float* p2    = (const float*)d_in[13];
    const float* Wl    = (const float*)d_in[14];
    const float* bl    = (const float*)d_in[15];
    float* out = (float*)d_out;

    k1<<<NN, 512>>>(enc, ea, W_enc, b_enc, W1, b1, p1, We, pe, b2, Wl, bl, out);

    cudaLaunchAttribute attr[1];
    attr[0].id = cudaLaunchAttributeProgrammaticStreamSerialization;
    attr[0].val.programmaticStreamSerializationAllowed = 1;

    {
        cudaLaunchConfig_t cfg = {};
        cfg.gridDim = dim3(NN + 2);
        cfg.blockDim = dim3(128);
        cfg.attrs = attr;
        cfg.numAttrs = 1;
        cfg.stream = 0;
        cudaLaunchKernelEx(&cfg, k2, W2, Wl);
    }
    {
        cudaLaunchConfig_t cfg = {};
        cfg.gridDim = dim3(NN);
        cfg.blockDim = dim3(128);
        cfg.attrs = attr;
        cfg.numAttrs = 1;
        cfg.stream = 0;
        cudaLaunchKernelEx(&cfg, k3, be, p2, out);
    }
}